// round 13
// baseline (speedup 1.0000x reference)
#include <cuda_runtime.h>
#include <cstdint>

// LSTM CellForecaster: B=4096, T=512, H=128, IN=2, OUT=2, FUTURE=50
// 147 persistent CTAs x 512 threads, BB=28 batch rows/CTA (tail-guarded).
// Warp grid: Nb=4 (=SMSP) x Ng=2 gate-halves x Nk=2 k-halves.
// W_hh pre-transposed into lane-major g_Wt, streamed from L2 via LDG.128.
// R13 vs R12: (1) W prefetch rolls across chunk boundary (chunk-start L2
// latency overlapped with store/bar/combine), (2) hv wraparound reused across
// chunks (reload only at ch0), (3) x prefetched one step ahead, (4) scr
// partials horizontally-added floats (1 wf per STS/LDS).

#define HID    128
#define GATES  512
#define BB     28
#define NCTA   147
#define BTOT   4096
#define TENC   512
#define FUT    50
#define NSTEP  (TENC + FUT)
#define THREADS 512
#define TPITCH 132       // hT row pitch (floats)

// Transposed W_hh: idx = ((((ch*2+gq)*2+kq)*16 + it)*2 + pair)*32 + tx, 4 floats each.
__device__ float g_Wt[GATES * HID];   // 256 KB

struct alignas(16) SmemLayout {
    float hT[BB * TPITCH];            // h batch-major: hT[b][k]
    float scr[2][2][2][4][7][32];     // [parity][ownkq][gq][ty][p][tx] (hsummed)
    float bias[GATES];                // b_ih + b_hh
    float wih[GATES * 2];
    float fcw[2 * HID];
    float fcb[2];
    float xin[BB * 2];                // step input (x_t or fed-back y)
};

__device__ __forceinline__ void upk2(unsigned long long v, float& x, float& y) {
    asm("mov.b64 {%0,%1}, %2;" : "=f"(x), "=f"(y) : "l"(v));
}
__device__ __forceinline__ unsigned long long fma2(unsigned long long a,
                                                   unsigned long long b,
                                                   unsigned long long c) {
    unsigned long long d;
    asm("fma.rn.f32x2 %0, %1, %2, %3;" : "=l"(d) : "l"(a), "l"(b), "l"(c));
    return d;
}
__device__ __forceinline__ float hsum2(unsigned long long v) {
    float a, b; upk2(v, a, b); return a + b;
}
__device__ __forceinline__ float sigf(float x) { return 1.f / (1.f + __expf(-x)); }
__device__ __forceinline__ float tanh_(float x) { return 2.f / (1.f + __expf(-2.f * x)) - 1.f; }

// ---- prologue: permute W_hh into lane-major streaming layout ----
__global__ void transpose_whh_kernel(const float* __restrict__ Whh) {
    int idx = blockIdx.x * blockDim.x + threadIdx.x;   // 16384 float4 groups
    if (idx < GATES * HID / 4) {
        int tx   = idx & 31;
        int pair = (idx >> 5) & 1;
        int it   = (idx >> 6) & 15;
        int kq   = (idx >> 10) & 1;
        int gq   = (idx >> 11) & 1;
        int ch   = (idx >> 12) & 3;
        int row  = ch * 128 + gq * 64 + pair * 32 + tx;
        int k    = kq * 64 + it * 4;
        float4 v = *reinterpret_cast<const float4*>(Whh + row * HID + k);
        *reinterpret_cast<float4*>(g_Wt + (size_t)idx * 4) = v;
    }
}

__global__ void __launch_bounds__(THREADS, 1)
lstm_forecast_kernel(const float* __restrict__ x,
                     const float* __restrict__ Wih,
                     const float* __restrict__ bih,
                     const float* __restrict__ bhh,
                     const float* __restrict__ fcw,
                     const float* __restrict__ fcb,
                     float* __restrict__ out)
{
    extern __shared__ char smraw[];
    SmemLayout& sm = *reinterpret_cast<SmemLayout*>(smraw);

    const int tid  = threadIdx.x;
    const int bat0 = blockIdx.x * BB;
    const int tx   = tid & 31;           // lane
    const int wrp  = tid >> 5;           // 0..15
    const int ty   = wrp & 3;            // batch group (7 rows) == SMSP
    const int gq   = (wrp >> 2) & 1;     // gate half (64 rows)
    const int kq   = wrp >> 3;           // k half (64 k-values)
    const int row0 = gq * 64 + tx;       // gate rows: row0 (gi0), row0+32 (gi1)
    const int bt0  = ty * 7;
    const int kb   = kq * 64;
    const int rh   = row0 + 32 * kq;     // OWNED hidden/gate row (epilogue)

    // per-(gq,kq) W stream base within a chunk block (ch stride = 16384 floats)
    const float* wbase = g_Wt + (size_t)(gq * 2 + kq) * 4096 + tx * 4;

    // ---- one-time init ----
    for (int i = tid; i < BB * TPITCH; i += THREADS) sm.hT[i] = 0.f;
    for (int g = tid; g < GATES; g += THREADS) {
        sm.bias[g]      = bih[g] + bhh[g];
        sm.wih[g*2 + 0] = Wih[g*2 + 0];
        sm.wih[g*2 + 1] = Wih[g*2 + 1];
    }
    for (int i = tid; i < 2 * HID; i += THREADS) sm.fcw[i] = fcw[i];
    if (tid < 2) sm.fcb[tid] = fcb[tid];

    // owned state: 1 gate/hidden row (rh) x 7 batch
    float creg[7], ti[7];
    #pragma unroll
    for (int p = 0; p < 7; p++) { creg[p] = 0.f; ti[p] = 0.f; }

    // x prefetch state (lanes tid<56 own one (b,io) slot; xin index == tid)
    const bool xown = tid < 2 * BB;
    const bool xok  = xown && (bat0 + (tid >> 1) < BTOT);
    const float* xptr = x + (size_t)(bat0 + (tid >> 1)) * (TENC * 2) + (tid & 1);
    float xr = xok ? xptr[0] : 0.f;    // step 0

    // W prefetch pipeline, live across chunks AND steps (starts at s0/ch0/it0,1)
    ulonglong2 wa0 = *reinterpret_cast<const ulonglong2*>(wbase);
    ulonglong2 wa1 = *reinterpret_cast<const ulonglong2*>(wbase + 128);
    ulonglong2 wb0 = *reinterpret_cast<const ulonglong2*>(wbase + 256);
    ulonglong2 wb1 = *reinterpret_cast<const ulonglong2*>(wbase + 384);

    __syncthreads();

    for (int s = 0; s < NSTEP; s++) {
        // ---- step input: x_t (encode, prefetched) or fc head (forecast) ----
        if (s < TENC) {
            if (xown) sm.xin[tid] = xr;
        } else {
            if (xown) {
                const int b = tid >> 1, io = tid & 1;
                float acc = sm.fcb[io];
                const float* fr = &sm.fcw[io * HID];
                const float* hr = &sm.hT[b * TPITCH];
                #pragma unroll 8
                for (int k = 0; k < HID; k += 4) {
                    float4 hq = *reinterpret_cast<const float4*>(&hr[k]);
                    float4 fq = *reinterpret_cast<const float4*>(&fr[k]);
                    acc += hq.x*fq.x + hq.y*fq.y + hq.z*fq.z + hq.w*fq.w;
                }
                sm.xin[tid] = xok ? acc : 0.f;
                if (xok) out[(size_t)(bat0 + b) * (FUT * 2) + (s - TENC) * 2 + io] = acc;
            }
        }
        __syncthreads();   // xin visible (hT stable from end-of-step sync)

        // prefetch next step's x (latency hides behind the whole step)
        if (xok && s + 1 < TENC) xr = xptr[(s + 1) * 2];

        ulonglong2 hv[7];   // reloaded at ch0; wraparound carries across chunks

        #pragma unroll 1
        for (int ch = 0; ch < 4; ch++) {
            unsigned long long acc0[7], acc1[7];
            #pragma unroll
            for (int p = 0; p < 7; p++) { acc0[p] = 0ull; acc1[p] = 0ull; }

            const float* wp_cur = wbase + (size_t)ch * 16384;
            const float* wp_nxt = wbase + (size_t)((ch + 1) & 3) * 16384;

            if (ch == 0) {
                #pragma unroll
                for (int p = 0; p < 7; p++)
                    hv[p] = *reinterpret_cast<const ulonglong2*>(&sm.hT[(bt0 + p) * TPITCH + kb]);
            }

            #pragma unroll
            for (int it = 0; it < 16; it++) {
                const int knxt = kb + 4 * ((it + 1) & 15);   // wraps to kb at it=15
                ulonglong2 w0 = wa0, w1 = wa1;
                wa0 = wb0; wa1 = wb1;
                {   // prefetch it+2; rolls into next chunk (next step for ch3)
                    const float* wsrc = (it + 2 < 16) ? (wp_cur + (size_t)(it + 2) * 256)
                                                      : (wp_nxt + (size_t)(it - 14) * 256);
                    wb0 = *reinterpret_cast<const ulonglong2*>(wsrc);
                    wb1 = *reinterpret_cast<const ulonglong2*>(wsrc + 128);
                }
                #pragma unroll
                for (int p = 0; p < 7; p++) {
                    ulonglong2 h = hv[p];
                    hv[p] = *reinterpret_cast<const ulonglong2*>(&sm.hT[(bt0 + p) * TPITCH + knxt]);
                    acc0[p] = fma2(w0.x, h.x, acc0[p]);
                    acc0[p] = fma2(w0.y, h.y, acc0[p]);
                    acc1[p] = fma2(w1.x, h.x, acc1[p]);
                    acc1[p] = fma2(w1.y, h.y, acc1[p]);
                }
            }

            // ---- exchange non-owned gi partial (horizontally added, float) ----
            // kq0 owns gi0 (ships acc1 to kq1's slot); kq1 owns gi1 (ships acc0).
            {
                float (*dst)[32] = sm.scr[ch & 1][kq ^ 1][gq][ty];
                #pragma unroll
                for (int p = 0; p < 7; p++)
                    dst[p][tx] = hsum2(kq ? acc0[p] : acc1[p]);
            }
            __syncthreads();   // partials visible; all hT reads for ch done

            // ---- combine + bias + x@W_ih^T + pointwise on OWNED row rh ----
            {
                float (*src)[32] = sm.scr[ch & 1][kq][gq][ty];
                const int G   = ch * 128 + rh;
                const float bsv = sm.bias[G];
                const float w0 = sm.wih[G * 2], w1 = sm.wih[G * 2 + 1];
                #pragma unroll
                for (int p = 0; p < 7; p++) {
                    float own = hsum2(kq ? acc1[p] : acc0[p]);
                    const int b = bt0 + p;
                    float gate = own + src[p][tx] + bsv
                               + sm.xin[b*2]*w0 + sm.xin[b*2+1]*w1;
                    if (ch == 0) {                         // i
                        ti[p] = sigf(gate);
                    } else if (ch == 1) {                  // f
                        creg[p] *= sigf(gate);
                    } else if (ch == 2) {                  // g
                        creg[p] += ti[p] * tanh_(gate);
                    } else {                               // o: hT dead now
                        sm.hT[b * TPITCH + rh] = sigf(gate) * tanh_(creg[p]);
                    }
                }
            }
        }
        __syncthreads();   // new hT visible for fc-head / next step
    }
}

extern "C" void kernel_launch(void* const* d_in, const int* in_sizes, int n_in,
                              void* d_out, int out_size) {
    const float* x    = (const float*)d_in[0];
    const float* Wih  = (const float*)d_in[1];
    const float* Whh  = (const float*)d_in[2];
    const float* bih  = (const float*)d_in[3];
    const float* bhh  = (const float*)d_in[4];
    const float* fcw  = (const float*)d_in[5];
    const float* fcb  = (const float*)d_in[6];
    float* out = (float*)d_out;

    transpose_whh_kernel<<<(GATES * HID / 4 + 255) / 256, 256>>>(Whh);

    const int smem_bytes = (int)sizeof(SmemLayout);
    cudaFuncSetAttribute(lstm_forecast_kernel,
                         cudaFuncAttributeMaxDynamicSharedMemorySize, smem_bytes);

    lstm_forecast_kernel<<<NCTA, THREADS, smem_bytes>>>(
        x, Wih, bih, bhh, fcw, fcb, out);
}

// round 14
// speedup vs baseline: 1.0514x; 1.0514x over previous
#include <cuda_runtime.h>
#include <cstdint>

// LSTM CellForecaster: B=4096, T=512, H=128, IN=2, OUT=2, FUTURE=50
// R14: 294 persistent CTAs x 256 threads, 2 CTAs/SM (independent batch
// slices interleave: one CTA's GEMM hides the other's barriers/epilogue).
// Per-CTA warp grid: Nb=2 x Ng=2 x Nk=2 (8 warps); per-thread tile identical
// to R12 (2 gate rows x 7 batch, k-half). W_hh pre-transposed lane-major in
// g_Wt, streamed from L2 via LDG.128 + depth-2 register prefetch.
// Keeps from R13: float/hsum scr exchange, x prefetch. Reverts: cross-chunk
// W rollover + hv carry (ALU bloat).

#define HID    128
#define GATES  512
#define BB     14
#define NCTA   294
#define BTOT   4096
#define TENC   512
#define FUT    50
#define NSTEP  (TENC + FUT)
#define THREADS 256
#define TPITCH 132       // hT row pitch (floats)

// Transposed W_hh: idx = ((((ch*2+gq)*2+kq)*16 + it)*2 + pair)*32 + tx, 4 floats each.
__device__ float g_Wt[GATES * HID];   // 256 KB

struct alignas(16) SmemLayout {
    float hT[BB * TPITCH];            // h batch-major: hT[b][k]
    float scr[2][2][2][2][7][32];     // [parity][ownkq][gq][ty][p][tx] (hsummed)
    float bias[GATES];                // b_ih + b_hh
    float wih[GATES * 2];
    float fcw[2 * HID];
    float fcb[2];
    float xin[BB * 2];                // step input (x_t or fed-back y)
};

__device__ __forceinline__ void upk2(unsigned long long v, float& x, float& y) {
    asm("mov.b64 {%0,%1}, %2;" : "=f"(x), "=f"(y) : "l"(v));
}
__device__ __forceinline__ unsigned long long fma2(unsigned long long a,
                                                   unsigned long long b,
                                                   unsigned long long c) {
    unsigned long long d;
    asm("fma.rn.f32x2 %0, %1, %2, %3;" : "=l"(d) : "l"(a), "l"(b), "l"(c));
    return d;
}
__device__ __forceinline__ float hsum2(unsigned long long v) {
    float a, b; upk2(v, a, b); return a + b;
}
__device__ __forceinline__ float sigf(float x) { return 1.f / (1.f + __expf(-x)); }
__device__ __forceinline__ float tanh_(float x) { return 2.f / (1.f + __expf(-2.f * x)) - 1.f; }

// ---- prologue: permute W_hh into lane-major streaming layout ----
__global__ void transpose_whh_kernel(const float* __restrict__ Whh) {
    int idx = blockIdx.x * blockDim.x + threadIdx.x;   // 16384 float4 groups
    if (idx < GATES * HID / 4) {
        int tx   = idx & 31;
        int pair = (idx >> 5) & 1;
        int it   = (idx >> 6) & 15;
        int kq   = (idx >> 10) & 1;
        int gq   = (idx >> 11) & 1;
        int ch   = (idx >> 12) & 3;
        int row  = ch * 128 + gq * 64 + pair * 32 + tx;
        int k    = kq * 64 + it * 4;
        float4 v = *reinterpret_cast<const float4*>(Whh + row * HID + k);
        *reinterpret_cast<float4*>(g_Wt + (size_t)idx * 4) = v;
    }
}

__global__ void __launch_bounds__(THREADS, 2)
lstm_forecast_kernel(const float* __restrict__ x,
                     const float* __restrict__ Wih,
                     const float* __restrict__ bih,
                     const float* __restrict__ bhh,
                     const float* __restrict__ fcw,
                     const float* __restrict__ fcb,
                     float* __restrict__ out)
{
    extern __shared__ char smraw[];
    SmemLayout& sm = *reinterpret_cast<SmemLayout*>(smraw);

    const int tid  = threadIdx.x;
    const int bat0 = blockIdx.x * BB;
    const int tx   = tid & 31;           // lane
    const int wrp  = tid >> 5;           // 0..7
    const int ty   = wrp & 1;            // batch group (7 rows)
    const int gq   = (wrp >> 1) & 1;     // gate half (64 rows)
    const int kq   = wrp >> 2;           // k half (64 k-values)
    const int row0 = gq * 64 + tx;       // gate rows: row0 (gi0), row0+32 (gi1)
    const int bt0  = ty * 7;
    const int kb   = kq * 64;
    const int rh   = row0 + 32 * kq;     // OWNED hidden/gate row (epilogue)

    // per-(gq,kq) W stream base within a chunk block (ch stride = 16384 floats)
    const float* wbase = g_Wt + (size_t)(gq * 2 + kq) * 4096 + tx * 4;

    // ---- one-time init ----
    for (int i = tid; i < BB * TPITCH; i += THREADS) sm.hT[i] = 0.f;
    for (int g = tid; g < GATES; g += THREADS) {
        sm.bias[g]      = bih[g] + bhh[g];
        sm.wih[g*2 + 0] = Wih[g*2 + 0];
        sm.wih[g*2 + 1] = Wih[g*2 + 1];
    }
    for (int i = tid; i < 2 * HID; i += THREADS) sm.fcw[i] = fcw[i];
    if (tid < 2) sm.fcb[tid] = fcb[tid];

    // owned state: 1 gate/hidden row (rh) x 7 batch
    float creg[7], ti[7];
    #pragma unroll
    for (int p = 0; p < 7; p++) { creg[p] = 0.f; ti[p] = 0.f; }

    // x prefetch state (lanes tid<28 own one (b,io) slot; xin index == tid)
    const bool xown = tid < 2 * BB;
    const bool xok  = xown && (bat0 + (tid >> 1) < BTOT);
    const float* xptr = x + (size_t)(bat0 + (tid >> 1)) * (TENC * 2) + (tid & 1);
    float xr = xok ? xptr[0] : 0.f;    // step 0

    __syncthreads();

    for (int s = 0; s < NSTEP; s++) {
        // ---- step input: x_t (encode, prefetched) or fc head (forecast) ----
        if (s < TENC) {
            if (xown) sm.xin[tid] = xr;
        } else {
            if (xown) {
                const int b = tid >> 1, io = tid & 1;
                float acc = sm.fcb[io];
                const float* fr = &sm.fcw[io * HID];
                const float* hr = &sm.hT[b * TPITCH];
                #pragma unroll 8
                for (int k = 0; k < HID; k += 4) {
                    float4 hq = *reinterpret_cast<const float4*>(&hr[k]);
                    float4 fq = *reinterpret_cast<const float4*>(&fr[k]);
                    acc += hq.x*fq.x + hq.y*fq.y + hq.z*fq.z + hq.w*fq.w;
                }
                sm.xin[tid] = xok ? acc : 0.f;
                if (xok) out[(size_t)(bat0 + b) * (FUT * 2) + (s - TENC) * 2 + io] = acc;
            }
        }
        __syncthreads();   // xin visible (hT stable from end-of-step sync)

        // prefetch next step's x (latency hides behind the whole step)
        if (xok && s + 1 < TENC) xr = xptr[(s + 1) * 2];

        #pragma unroll 1
        for (int ch = 0; ch < 4; ch++) {
            // ---- partial GEMM over this warp's k-half; W streamed from L2 ----
            unsigned long long acc0[7], acc1[7];
            #pragma unroll
            for (int p = 0; p < 7; p++) { acc0[p] = 0ull; acc1[p] = 0ull; }

            const float* wp = wbase + (size_t)ch * 16384;  // [it][pair][tx][4]

            // depth-2 W prefetch (LDG.128, 512B/warp contiguous)
            ulonglong2 wa0 = *reinterpret_cast<const ulonglong2*>(wp);
            ulonglong2 wa1 = *reinterpret_cast<const ulonglong2*>(wp + 128);
            ulonglong2 wb0 = *reinterpret_cast<const ulonglong2*>(wp + 256);
            ulonglong2 wb1 = *reinterpret_cast<const ulonglong2*>(wp + 384);

            // h operands: rotate-in-place LDS pipeline
            ulonglong2 hv[7];
            #pragma unroll
            for (int p = 0; p < 7; p++)
                hv[p] = *reinterpret_cast<const ulonglong2*>(&sm.hT[(bt0 + p) * TPITCH + kb]);

            #pragma unroll
            for (int it = 0; it < 16; it++) {
                const int knxt = kb + 4 * ((it + 1) & 15);   // wrap: harmless
                ulonglong2 w0 = wa0, w1 = wa1;
                wa0 = wb0; wa1 = wb1;
                if (it + 2 < 16) {
                    const float* wn = wp + (size_t)(it + 2) * 256;
                    wb0 = *reinterpret_cast<const ulonglong2*>(wn);
                    wb1 = *reinterpret_cast<const ulonglong2*>(wn + 128);
                }
                #pragma unroll
                for (int p = 0; p < 7; p++) {
                    ulonglong2 h = hv[p];
                    hv[p] = *reinterpret_cast<const ulonglong2*>(&sm.hT[(bt0 + p) * TPITCH + knxt]);
                    acc0[p] = fma2(w0.x, h.x, acc0[p]);
                    acc0[p] = fma2(w0.y, h.y, acc0[p]);
                    acc1[p] = fma2(w1.x, h.x, acc1[p]);
                    acc1[p] = fma2(w1.y, h.y, acc1[p]);
                }
            }

            // ---- exchange non-owned gi partial (horizontally added, float) ----
            // kq0 owns gi0 (ships acc1 to kq1's slot); kq1 owns gi1 (ships acc0).
            {
                float (*dst)[32] = sm.scr[ch & 1][kq ^ 1][gq][ty];
                #pragma unroll
                for (int p = 0; p < 7; p++)
                    dst[p][tx] = hsum2(kq ? acc0[p] : acc1[p]);
            }
            __syncthreads();   // partials visible; all hT reads for ch done

            // ---- combine + bias + x@W_ih^T + pointwise on OWNED row rh ----
            {
                float (*src)[32] = sm.scr[ch & 1][kq][gq][ty];
                const int G   = ch * 128 + rh;
                const float bsv = sm.bias[G];
                const float w0 = sm.wih[G * 2], w1 = sm.wih[G * 2 + 1];
                #pragma unroll
                for (int p = 0; p < 7; p++) {
                    float own = hsum2(kq ? acc1[p] : acc0[p]);
                    const int b = bt0 + p;
                    float gate = own + src[p][tx] + bsv
                               + sm.xin[b*2]*w0 + sm.xin[b*2+1]*w1;
                    if (ch == 0) {                         // i
                        ti[p] = sigf(gate);
                    } else if (ch == 1) {                  // f
                        creg[p] *= sigf(gate);
                    } else if (ch == 2) {                  // g
                        creg[p] += ti[p] * tanh_(gate);
                    } else {                               // o: hT dead now
                        sm.hT[b * TPITCH + rh] = sigf(gate) * tanh_(creg[p]);
                    }
                }
            }
        }
        __syncthreads();   // new hT visible for fc-head / next step
    }
}

extern "C" void kernel_launch(void* const* d_in, const int* in_sizes, int n_in,
                              void* d_out, int out_size) {
    const float* x    = (const float*)d_in[0];
    const float* Wih  = (const float*)d_in[1];
    const float* Whh  = (const float*)d_in[2];
    const float* bih  = (const float*)d_in[3];
    const float* bhh  = (const float*)d_in[4];
    const float* fcw  = (const float*)d_in[5];
    const float* fcb  = (const float*)d_in[6];
    float* out = (float*)d_out;

    transpose_whh_kernel<<<(GATES * HID / 4 + 255) / 256, 256>>>(Whh);

    const int smem_bytes = (int)sizeof(SmemLayout);
    cudaFuncSetAttribute(lstm_forecast_kernel,
                         cudaFuncAttributeMaxDynamicSharedMemorySize, smem_bytes);

    lstm_forecast_kernel<<<NCTA, THREADS, smem_bytes>>>(
        x, Wih, bih, bhh, fcw, fcb, out);
}

// round 16
// speedup vs baseline: 1.6738x; 1.5921x over previous
#include <cuda_runtime.h>
#include <cuda_fp16.h>
#include <cstdint>

// LSTM CellForecaster via HMMA (mma.sync m16n8k16 f16->f32), sm_103-safe.
// 128 CTAs x 256 threads, BB=32 (4096 = 128*32 exact). 8 warps: warp w owns
// M-tile w (16 gate rows) of every chunk, all 4 N-tiles (32 batch).
// Precision: W and h split into f16 hi+lo; D = Whi*hhi + Whi*hlo + Wlo*hhi
// (dropped Wlo*hlo ~ 2^-22). Accumulate fp32 in registers; exact fp32 epilogue.
// W pre-packed into 8x8 ldmatrix tiles: Whi (4 chunks, 128KB) persistent in
// smem; Wlo streamed per chunk (32KB, double-buffered cp.async).
// h stored as packed f16 hi/lo B-tiles, rebuilt each step.

#define HID    128
#define GATES  512
#define BB     32
#define NCTA   128
#define TENC   512
#define FUT    50
#define NSTEP  (TENC + FUT)
#define THREADS 256

__device__ __half g_Whi[4][16384];   // packed tile images, 32KB per chunk
__device__ __half g_Wlo[4][16384];

struct alignas(16) Smem {
    __half Whi[4][16384];   // 131072 B, persistent
    __half Wlo[2][16384];   //  65536 B, double buffer
    __half Bhi[4096];       //   8192 B, h hi tiles (packed 8x8)
    __half Blo[4096];       //   8192 B
    float bias[GATES];
    float wih[GATES * 2];
    float fcw[2 * HID];
    float fcb[2];
    float xin[BB * 2];
};

__device__ __forceinline__ uint32_t smem_u32(const void* p) {
    uint32_t a;
    asm("{ .reg .u64 t; cvta.to.shared.u64 t, %1; cvt.u32.u64 %0, t; }" : "=r"(a) : "l"(p));
    return a;
}
__device__ __forceinline__ void cpa16(uint32_t dst, const void* src) {
    asm volatile("cp.async.cg.shared.global [%0], [%1], 16;" :: "r"(dst), "l"(src));
}
#define CP_COMMIT() asm volatile("cp.async.commit_group;")
#define CP_WAIT0()  asm volatile("cp.async.wait_group 0;")

#define LDSM4(r, addr) \
    asm volatile("ldmatrix.sync.aligned.m8n8.x4.shared.b16 {%0,%1,%2,%3}, [%4];" \
        : "=r"((r)[0]), "=r"((r)[1]), "=r"((r)[2]), "=r"((r)[3]) : "r"(addr))

#define MMA16816(d, a, b0, b1) \
    asm volatile("mma.sync.aligned.m16n8k16.row.col.f32.f16.f16.f32 " \
        "{%0,%1,%2,%3},{%4,%5,%6,%7},{%8,%9},{%0,%1,%2,%3};" \
        : "+f"((d)[0]), "+f"((d)[1]), "+f"((d)[2]), "+f"((d)[3]) \
        : "r"((a)[0]), "r"((a)[1]), "r"((a)[2]), "r"((a)[3]), "r"(b0), "r"(b1))

__device__ __forceinline__ float sigf(float x) { return 1.f / (1.f + __expf(-x)); }
__device__ __forceinline__ float tanh_(float x) { return 2.f / (1.f + __expf(-2.f * x)) - 1.f; }

// packed-tile half offsets
__device__ __forceinline__ int a_off(int r, int k) {   // A tile [128 rows][128 k]
    return (((r >> 4) * 8 + (k >> 4)) * 4 + ((r >> 3) & 1) + ((k >> 3) & 1) * 2) * 64
           + (r & 7) * 8 + (k & 7);
}
__device__ __forceinline__ int b_off(int b, int k) {   // B tile [32 batch][128 k]
    return (((b >> 4) * 8 + (k >> 4)) * 4 + ((b >> 3) & 1) * 2 + ((k >> 3) & 1)) * 64
           + (b & 7) * 8 + (k & 7);
}

// ---- prologue: split W_hh into f16 hi/lo packed tile images ----
__global__ void prep_whh(const float* __restrict__ Whh) {
    int i = blockIdx.x * blockDim.x + threadIdx.x;
    if (i >= GATES * HID) return;
    int g = i >> 7, k = i & 127;
    int ch = g >> 7, r = g & 127;
    float v = Whh[i];
    __half hi = __float2half_rn(v);
    __half lo = __float2half_rn(v - __half2float(hi));
    int off = a_off(r, k);
    g_Whi[ch][off] = hi;
    g_Wlo[ch][off] = lo;
}

__global__ void __launch_bounds__(THREADS, 1)
lstm_forecast_kernel(const float* __restrict__ x,
                     const float* __restrict__ Wih,
                     const float* __restrict__ bih,
                     const float* __restrict__ bhh,
                     const float* __restrict__ fcw,
                     const float* __restrict__ fcb,
                     float* __restrict__ out)
{
    extern __shared__ char smraw[];
    Smem& sm = *reinterpret_cast<Smem*>(smraw);

    const int tid  = threadIdx.x;
    const int tx   = tid & 31;
    const int w    = tid >> 5;        // M-tile (16 gate rows)
    const int gid  = tx >> 2;
    const int tq   = tx & 3;
    const int r0   = w * 16 + gid;    // owned rows: r0, r0+8 (per chunk & hidden)
    const int bat0 = blockIdx.x * BB;

    const uint32_t smb     = smem_u32(&sm);
    const uint32_t laneoff = (uint32_t)((tx >> 3) * 128 + (tx & 7) * 16);
    const uint32_t whiB = smb;
    const uint32_t wloB = smb + 131072u;
    const uint32_t bhiB = smb + 196608u;
    const uint32_t bloB = smb + 204800u;

    // ---- one-time init ----
    for (int i = tid; i < 4096; i += THREADS) {
        sm.Bhi[i] = __float2half(0.f);
        sm.Blo[i] = __float2half(0.f);
    }
    for (int g = tid; g < GATES; g += THREADS) {
        sm.bias[g]      = bih[g] + bhh[g];
        sm.wih[g*2 + 0] = Wih[g*2 + 0];
        sm.wih[g*2 + 1] = Wih[g*2 + 1];
    }
    for (int i = tid; i < 2 * HID; i += THREADS) sm.fcw[i] = fcw[i];
    if (tid < 2) sm.fcb[tid] = fcb[tid];

    // stage Whi (all 4 chunks) once + Wlo chunk 0
    {
        const char* src = (const char*)g_Whi;
        #pragma unroll
        for (int r = 0; r < 32; r++) {
            int e = tid + THREADS * r;            // 8192 x 16B
            cpa16(whiB + (uint32_t)e * 16u, src + (size_t)e * 16);
        }
        CP_COMMIT();
        const char* s2 = (const char*)&g_Wlo[0][0];
        #pragma unroll
        for (int r = 0; r < 8; r++) {
            int e = tid + THREADS * r;            // 2048 x 16B
            cpa16(wloB + (uint32_t)e * 16u, s2 + (size_t)e * 16);
        }
        CP_COMMIT();
    }

    float creg[16], ti[16];
    #pragma unroll
    for (int i = 0; i < 16; i++) { creg[i] = 0.f; ti[i] = 0.f; }

    const bool xown = tid < 2 * BB;
    const float* xptr = x + (size_t)(bat0 + (tid >> 1)) * (TENC * 2) + (tid & 1);
    float xr = xown ? xptr[0] : 0.f;

    CP_WAIT0();
    __syncthreads();

    for (int s = 0; s < NSTEP; s++) {
        // ---- step input: x_t or fc head (h = Bhi + Blo) ----
        if (s < TENC) {
            if (xown) sm.xin[tid] = xr;
        } else if (xown) {
            const int b = tid >> 1, io = tid & 1;
            float acc = sm.fcb[io];
            #pragma unroll
            for (int kb = 0; kb < 16; kb++) {
                int off = b_off(b, kb * 8);
                uint4 vh = *(const uint4*)&sm.Bhi[off];
                uint4 vl = *(const uint4*)&sm.Blo[off];
                const __half* ph = (const __half*)&vh;
                const __half* pl = (const __half*)&vl;
                const float* fw = &sm.fcw[io * HID + kb * 8];
                #pragma unroll
                for (int j = 0; j < 8; j++)
                    acc += (__half2float(ph[j]) + __half2float(pl[j])) * fw[j];
            }
            sm.xin[tid] = acc;
            out[(size_t)(bat0 + b) * (FUT * 2) + (s - TENC) * 2 + io] = acc;
        }
        __syncthreads();
        if (xown && s + 1 < TENC) xr = xptr[(s + 1) * 2];

        float h16[16];

        #pragma unroll 1
        for (int ch = 0; ch < 4; ch++) {
            CP_WAIT0();        // Wlo[ch] landed
            __syncthreads();   // visible; prev lo buffer free
            if (!(s == NSTEP - 1 && ch == 3)) {
                const char* src = (const char*)&g_Wlo[(ch + 1) & 3][0];
                uint32_t dst = wloB + (uint32_t)((ch + 1) & 1) * 32768u;
                #pragma unroll
                for (int r = 0; r < 8; r++) {
                    int e = tid + THREADS * r;
                    cpa16(dst + (uint32_t)e * 16u, src + (size_t)e * 16);
                }
                CP_COMMIT();
            }

            float acc[4][4];
            #pragma unroll
            for (int nt = 0; nt < 4; nt++)
                #pragma unroll
                for (int j = 0; j < 4; j++) acc[nt][j] = 0.f;

            const uint32_t aHi = whiB + (uint32_t)ch * 32768u + (uint32_t)w * 4096u + laneoff;
            const uint32_t aLo = wloB + (uint32_t)(ch & 1) * 32768u + (uint32_t)w * 4096u + laneoff;
            const uint32_t bH0 = bhiB + laneoff, bH1 = bhiB + 4096u + laneoff;
            const uint32_t bL0 = bloB + laneoff, bL1 = bloB + 4096u + laneoff;

            #pragma unroll
            for (int ks = 0; ks < 8; ks++) {
                uint32_t ah[4], al[4], bh[8], bl[8];
                LDSM4(ah, aHi + (uint32_t)ks * 512u);
                LDSM4(al, aLo + (uint32_t)ks * 512u);
                LDSM4(bh,     bH0 + (uint32_t)ks * 512u);
                LDSM4(bh + 4, bH1 + (uint32_t)ks * 512u);
                LDSM4(bl,     bL0 + (uint32_t)ks * 512u);
                LDSM4(bl + 4, bL1 + (uint32_t)ks * 512u);
                #pragma unroll
                for (int nt = 0; nt < 4; nt++) {
                    MMA16816(acc[nt], ah, bh[2*nt], bh[2*nt + 1]);
                    MMA16816(acc[nt], ah, bl[2*nt], bl[2*nt + 1]);
                    MMA16816(acc[nt], al, bh[2*nt], bh[2*nt + 1]);
                }
            }

            // ---- exact fp32 epilogue on owned rows r0, r0+8 ----
            const int G0 = ch * 128 + r0, G1 = G0 + 8;
            const float bs0 = sm.bias[G0], bs1 = sm.bias[G1];
            const float w00 = sm.wih[2*G0], w01 = sm.wih[2*G0 + 1];
            const float w10 = sm.wih[2*G1], w11 = sm.wih[2*G1 + 1];
            #pragma unroll
            for (int nt = 0; nt < 4; nt++) {
                #pragma unroll
                for (int j = 0; j < 4; j++) {
                    const int b = nt * 8 + tq * 2 + (j & 1);
                    const float xa = sm.xin[2*b], xb = sm.xin[2*b + 1];
                    const float gate = acc[nt][j] +
                        ((j < 2) ? (bs0 + xa * w00 + xb * w01)
                                 : (bs1 + xa * w10 + xb * w11));
                    const int idx = nt * 4 + j;
                    if (ch == 0)      ti[idx]    = sigf(gate);
                    else if (ch == 1) creg[idx] *= sigf(gate);
                    else if (ch == 2) creg[idx] += ti[idx] * tanh_(gate);
                    else              h16[idx]   = sigf(gate) * tanh_(creg[idx]);
                }
            }
        }

        __syncthreads();   // all warps done reading B tiles (chunk 3)
        #pragma unroll
        for (int nt = 0; nt < 4; nt++) {
            #pragma unroll
            for (int j = 0; j < 4; j++) {
                const int b = nt * 8 + tq * 2 + (j & 1);
                const int k = (j < 2) ? r0 : (r0 + 8);
                const float v = h16[nt * 4 + j];
                __half hh = __float2half_rn(v);
                __half hl = __float2half_rn(v - __half2float(hh));
                const int off = b_off(b, k);
                sm.Bhi[off] = hh;
                sm.Blo[off] = hl;
            }
        }
        __syncthreads();   // new h tiles visible for next step / fc head
    }
}

extern "C" void kernel_launch(void* const* d_in, const int* in_sizes, int n_in,
                              void* d_out, int out_size) {
    const float* x    = (const float*)d_in[0];
    const float* Wih  = (const float*)d_in[1];
    const float* Whh  = (const float*)d_in[2];
    const float* bih  = (const float*)d_in[3];
    const float* bhh  = (const float*)d_in[4];
    const float* fcw  = (const float*)d_in[5];
    const float* fcb  = (const float*)d_in[6];
    float* out = (float*)d_out;

    prep_whh<<<(GATES * HID + 255) / 256, 256>>>(Whh);

    const int smem_bytes = (int)sizeof(Smem);
    cudaFuncSetAttribute(lstm_forecast_kernel,
                         cudaFuncAttributeMaxDynamicSharedMemorySize, smem_bytes);

    lstm_forecast_kernel<<<NCTA, THREADS, smem_bytes>>>(
        x, Wih, bih, bhh, fcw, fcb, out);
}

// round 17
// speedup vs baseline: 2.0442x; 1.2213x over previous
#include <cuda_runtime.h>
#include <cuda_fp16.h>
#include <cstdint>

// LSTM CellForecaster via HMMA (mma.sync m16n8k16 f16->f32), sm_103-safe.
// R17: 128 CTAs x 512 threads (16 warps = 4/SMSP for latency hiding).
// Warp = (M-tile mt 0..7) x (N-half 0..1): per-ks loop is 4 LDSM.x4 + 6 MMA.
// B-tile LDSM traffic unchanged vs R16; A-tile doubles (crossbar had slack).
// Precision: W,h split f16 hi+lo; D = Whi*hhi + Whi*hlo + Wlo*hhi (fp32 acc).
// Whi (4 chunks, 128KB) persistent in smem; Wlo streamed (32KB, dbl-buffered).
// h stored as packed f16 hi/lo B-tiles, rebuilt each step; exact fp32 epilogue.

#define HID    128
#define GATES  512
#define BB     32
#define NCTA   128
#define TENC   512
#define FUT    50
#define NSTEP  (TENC + FUT)
#define THREADS 512

__device__ __half g_Whi[4][16384];   // packed tile images, 32KB per chunk
__device__ __half g_Wlo[4][16384];

struct alignas(16) Smem {
    __half Whi[4][16384];   // 131072 B, persistent
    __half Wlo[2][16384];   //  65536 B, double buffer
    __half Bhi[4096];       //   8192 B, h hi tiles (packed 8x8)
    __half Blo[4096];       //   8192 B
    float bias[GATES];
    float wih[GATES * 2];
    float fcw[2 * HID];
    float fcb[2];
    float xin[BB * 2];
};

__device__ __forceinline__ uint32_t smem_u32(const void* p) {
    uint32_t a;
    asm("{ .reg .u64 t; cvta.to.shared.u64 t, %1; cvt.u32.u64 %0, t; }" : "=r"(a) : "l"(p));
    return a;
}
__device__ __forceinline__ void cpa16(uint32_t dst, const void* src) {
    asm volatile("cp.async.cg.shared.global [%0], [%1], 16;" :: "r"(dst), "l"(src));
}
#define CP_COMMIT() asm volatile("cp.async.commit_group;")
#define CP_WAIT0()  asm volatile("cp.async.wait_group 0;")

#define LDSM4(r, addr) \
    asm volatile("ldmatrix.sync.aligned.m8n8.x4.shared.b16 {%0,%1,%2,%3}, [%4];" \
        : "=r"((r)[0]), "=r"((r)[1]), "=r"((r)[2]), "=r"((r)[3]) : "r"(addr))

#define MMA16816(d, a, b0, b1) \
    asm volatile("mma.sync.aligned.m16n8k16.row.col.f32.f16.f16.f32 " \
        "{%0,%1,%2,%3},{%4,%5,%6,%7},{%8,%9},{%0,%1,%2,%3};" \
        : "+f"((d)[0]), "+f"((d)[1]), "+f"((d)[2]), "+f"((d)[3]) \
        : "r"((a)[0]), "r"((a)[1]), "r"((a)[2]), "r"((a)[3]), "r"(b0), "r"(b1))

__device__ __forceinline__ float sigf(float x) { return 1.f / (1.f + __expf(-x)); }
__device__ __forceinline__ float tanh_(float x) { return 2.f / (1.f + __expf(-2.f * x)) - 1.f; }

// packed-tile half offsets
__device__ __forceinline__ int a_off(int r, int k) {   // A tile [128 rows][128 k]
    return (((r >> 4) * 8 + (k >> 4)) * 4 + ((r >> 3) & 1) + ((k >> 3) & 1) * 2) * 64
           + (r & 7) * 8 + (k & 7);
}
__device__ __forceinline__ int b_off(int b, int k) {   // B tile [32 batch][128 k]
    return (((b >> 4) * 8 + (k >> 4)) * 4 + ((b >> 3) & 1) * 2 + ((k >> 3) & 1)) * 64
           + (b & 7) * 8 + (k & 7);
}

// ---- prologue: split W_hh into f16 hi/lo packed tile images ----
__global__ void prep_whh(const float* __restrict__ Whh) {
    int i = blockIdx.x * blockDim.x + threadIdx.x;
    if (i >= GATES * HID) return;
    int g = i >> 7, k = i & 127;
    int ch = g >> 7, r = g & 127;
    float v = Whh[i];
    __half hi = __float2half_rn(v);
    __half lo = __float2half_rn(v - __half2float(hi));
    int off = a_off(r, k);
    g_Whi[ch][off] = hi;
    g_Wlo[ch][off] = lo;
}

__global__ void __launch_bounds__(THREADS, 1)
lstm_forecast_kernel(const float* __restrict__ x,
                     const float* __restrict__ Wih,
                     const float* __restrict__ bih,
                     const float* __restrict__ bhh,
                     const float* __restrict__ fcw,
                     const float* __restrict__ fcb,
                     float* __restrict__ out)
{
    extern __shared__ char smraw[];
    Smem& sm = *reinterpret_cast<Smem*>(smraw);

    const int tid   = threadIdx.x;
    const int tx    = tid & 31;
    const int w     = tid >> 5;        // 0..15
    const int mt    = w & 7;           // M-tile (16 gate rows)
    const int nhalf = w >> 3;          // N-half: batch 0..15 or 16..31
    const int gid   = tx >> 2;
    const int tq    = tx & 3;
    const int r0    = mt * 16 + gid;   // owned rows: r0, r0+8
    const int bat0  = blockIdx.x * BB;

    const uint32_t smb     = smem_u32(&sm);
    const uint32_t laneoff = (uint32_t)((tx >> 3) * 128 + (tx & 7) * 16);
    const uint32_t whiB = smb;
    const uint32_t wloB = smb + 131072u;
    const uint32_t bhiB = smb + 196608u;
    const uint32_t bloB = smb + 204800u;

    // ---- one-time init ----
    for (int i = tid; i < 4096; i += THREADS) {
        sm.Bhi[i] = __float2half(0.f);
        sm.Blo[i] = __float2half(0.f);
    }
    for (int g = tid; g < GATES; g += THREADS) {
        sm.bias[g]      = bih[g] + bhh[g];
        sm.wih[g*2 + 0] = Wih[g*2 + 0];
        sm.wih[g*2 + 1] = Wih[g*2 + 1];
    }
    for (int i = tid; i < 2 * HID; i += THREADS) sm.fcw[i] = fcw[i];
    if (tid < 2) sm.fcb[tid] = fcb[tid];

    // stage Whi (all 4 chunks) once + Wlo chunk 0
    {
        const char* src = (const char*)g_Whi;
        #pragma unroll
        for (int r = 0; r < 16; r++) {
            int e = tid + THREADS * r;            // 8192 x 16B
            cpa16(whiB + (uint32_t)e * 16u, src + (size_t)e * 16);
        }
        CP_COMMIT();
        const char* s2 = (const char*)&g_Wlo[0][0];
        #pragma unroll
        for (int r = 0; r < 4; r++) {
            int e = tid + THREADS * r;            // 2048 x 16B
            cpa16(wloB + (uint32_t)e * 16u, s2 + (size_t)e * 16);
        }
        CP_COMMIT();
    }

    float creg[8], ti[8];
    #pragma unroll
    for (int i = 0; i < 8; i++) { creg[i] = 0.f; ti[i] = 0.f; }

    const bool xown = tid < 2 * BB;
    const float* xptr = x + (size_t)(bat0 + (tid >> 1)) * (TENC * 2) + (tid & 1);
    float xr = xown ? xptr[0] : 0.f;

    CP_WAIT0();
    __syncthreads();

    for (int s = 0; s < NSTEP; s++) {
        // ---- step input: x_t or fc head (h = Bhi + Blo) ----
        if (s < TENC) {
            if (xown) sm.xin[tid] = xr;
        } else if (xown) {
            const int b = tid >> 1, io = tid & 1;
            float acc = sm.fcb[io];
            #pragma unroll
            for (int kb = 0; kb < 16; kb++) {
                int off = b_off(b, kb * 8);
                uint4 vh = *(const uint4*)&sm.Bhi[off];
                uint4 vl = *(const uint4*)&sm.Blo[off];
                const __half* ph = (const __half*)&vh;
                const __half* pl = (const __half*)&vl;
                const float* fw = &sm.fcw[io * HID + kb * 8];
                #pragma unroll
                for (int j = 0; j < 8; j++)
                    acc += (__half2float(ph[j]) + __half2float(pl[j])) * fw[j];
            }
            sm.xin[tid] = acc;
            out[(size_t)(bat0 + b) * (FUT * 2) + (s - TENC) * 2 + io] = acc;
        }
        __syncthreads();
        if (xown && s + 1 < TENC) xr = xptr[(s + 1) * 2];

        float h16[8];

        #pragma unroll 1
        for (int ch = 0; ch < 4; ch++) {
            CP_WAIT0();        // Wlo[ch] landed
            __syncthreads();   // visible; prev lo buffer free
            if (!(s == NSTEP - 1 && ch == 3)) {
                const char* src = (const char*)&g_Wlo[(ch + 1) & 3][0];
                uint32_t dst = wloB + (uint32_t)((ch + 1) & 1) * 32768u;
                #pragma unroll
                for (int r = 0; r < 4; r++) {
                    int e = tid + THREADS * r;
                    cpa16(dst + (uint32_t)e * 16u, src + (size_t)e * 16);
                }
                CP_COMMIT();
            }

            float acc[2][4];
            #pragma unroll
            for (int nt = 0; nt < 2; nt++)
                #pragma unroll
                for (int j = 0; j < 4; j++) acc[nt][j] = 0.f;

            const uint32_t aHi = whiB + (uint32_t)ch * 32768u + (uint32_t)mt * 4096u + laneoff;
            const uint32_t aLo = wloB + (uint32_t)(ch & 1) * 32768u + (uint32_t)mt * 4096u + laneoff;
            const uint32_t bH  = bhiB + (uint32_t)nhalf * 4096u + laneoff;
            const uint32_t bL  = bloB + (uint32_t)nhalf * 4096u + laneoff;

            #pragma unroll
            for (int ks = 0; ks < 8; ks++) {
                uint32_t ah[4], al[4], bh[4], bl[4];
                LDSM4(ah, aHi + (uint32_t)ks * 512u);
                LDSM4(al, aLo + (uint32_t)ks * 512u);
                LDSM4(bh, bH  + (uint32_t)ks * 512u);
                LDSM4(bl, bL  + (uint32_t)ks * 512u);
                #pragma unroll
                for (int nt = 0; nt < 2; nt++) {
                    MMA16816(acc[nt], ah, bh[2*nt], bh[2*nt + 1]);
                    MMA16816(acc[nt], ah, bl[2*nt], bl[2*nt + 1]);
                    MMA16816(acc[nt], al, bh[2*nt], bh[2*nt + 1]);
                }
            }

            // ---- exact fp32 epilogue on owned rows r0, r0+8 ----
            const int G0 = ch * 128 + r0, G1 = G0 + 8;
            const float bs0 = sm.bias[G0], bs1 = sm.bias[G1];
            const float w00 = sm.wih[2*G0], w01 = sm.wih[2*G0 + 1];
            const float w10 = sm.wih[2*G1], w11 = sm.wih[2*G1 + 1];
            #pragma unroll
            for (int nt = 0; nt < 2; nt++) {
                #pragma unroll
                for (int j = 0; j < 4; j++) {
                    const int b = nhalf * 16 + nt * 8 + tq * 2 + (j & 1);
                    const float xa = sm.xin[2*b], xb = sm.xin[2*b + 1];
                    const float gate = acc[nt][j] +
                        ((j < 2) ? (bs0 + xa * w00 + xb * w01)
                                 : (bs1 + xa * w10 + xb * w11));
                    const int idx = nt * 4 + j;
                    if (ch == 0)      ti[idx]    = sigf(gate);
                    else if (ch == 1) creg[idx] *= sigf(gate);
                    else if (ch == 2) creg[idx] += ti[idx] * tanh_(gate);
                    else              h16[idx]   = sigf(gate) * tanh_(creg[idx]);
                }
            }
        }

        __syncthreads();   // all warps done reading B tiles (chunk 3)
        #pragma unroll
        for (int nt = 0; nt < 2; nt++) {
            #pragma unroll
            for (int j = 0; j < 4; j++) {
                const int b = nhalf * 16 + nt * 8 + tq * 2 + (j & 1);
                const int k = (j < 2) ? r0 : (r0 + 8);
                const float v = h16[nt * 4 + j];
                __half hh = __float2half_rn(v);
                __half hl = __float2half_rn(v - __half2float(hh));
                const int off = b_off(b, k);
                sm.Bhi[off] = hh;
                sm.Blo[off] = hl;
            }
        }
        __syncthreads();   // new h tiles visible for next step / fc head
    }
}

extern "C" void kernel_launch(void* const* d_in, const int* in_sizes, int n_in,
                              void* d_out, int out_size) {
    const float* x    = (const float*)d_in[0];
    const float* Wih  = (const float*)d_in[1];
    const float* Whh  = (const float*)d_in[2];
    const float* bih  = (const float*)d_in[3];
    const float* bhh  = (const float*)d_in[4];
    const float* fcw  = (const float*)d_in[5];
    const float* fcb  = (const float*)d_in[6];
    float* out = (float*)d_out;

    prep_whh<<<(GATES * HID + 255) / 256, 256>>>(Whh);

    const int smem_bytes = (int)sizeof(Smem);
    cudaFuncSetAttribute(lstm_forecast_kernel,
                         cudaFuncAttributeMaxDynamicSharedMemorySize, smem_bytes);

    lstm_forecast_kernel<<<NCTA, THREADS, smem_bytes>>>(
        x, Wih, bih, bhh, fcw, fcb, out);
}